// round 7
// baseline (speedup 1.0000x reference)
#include <cuda_runtime.h>
#include <cuda_bf16.h>

// Entmax15: out = clip(X - tau*, 0)^2 with sum(out) = 1 per row,
// X = (masked_scores - rowmax) * 0.5.
//
// tau* via Newton on g(tau) = sqrt(f(tau)) - 1, f(tau) = sum max(X-tau,0)^2.
// g is convex left of the root (each piece of f is a quadratic K(t-c)^2+v,
// so 2 f f'' - f'^2 = 4Kv >= 0 and g' is continuous nondecreasing), hence
// Newton from tau=-1 is monotone, never overshoots: dlt = (S2-sqrt(S2))/S1.
//
// R7: 256 threads x 8 elems/thread, __launch_bounds__(256,8) caps regs at 32
// -> 64 warps/SM (100% occupancy) for maximum memory concurrency; the kernel
// is bandwidth-bound (R6: 768 MB / 6707 GB/s == measured 114.5 us exactly).
// redux.sync.f32 unavailable on sm_103a (R5) -> shuffle-tree warp reduce.

constexpr int S_LEN   = 2048;
constexpr int THREADS = 256;
constexpr int WARPS   = THREADS / 32;
constexpr int EPT     = S_LEN / THREADS;      // 8 elems per thread
constexpr int V4      = EPT / 4;              // 2 float4 per thread
constexpr float NEG_FILL = -1e4f;

__global__ void __launch_bounds__(THREADS, 8)
entmax15_kernel(const float* __restrict__ scores,
                const int*   __restrict__ mask,
                float*       __restrict__ out)
{
    const long long base = (long long)blockIdx.x * S_LEN;
    const float4* s4 = reinterpret_cast<const float4*>(scores + base);
    const int4*   m4 = reinterpret_cast<const int4*>(mask + base);
    float4*       o4 = reinterpret_cast<float4*>(out + base);

    const int tid  = threadIdx.x;
    const int warp = tid >> 5;
    const int lane = tid & 31;

    // ---- load 8 elems/thread, apply mask ----
    float x[EPT];
    #pragma unroll
    for (int v = 0; v < V4; ++v) {
        float4 a = s4[tid + v * THREADS];
        int4   m = m4[tid + v * THREADS];
        x[v * 4 + 0] = m.x ? a.x : NEG_FILL;
        x[v * 4 + 1] = m.y ? a.y : NEG_FILL;
        x[v * 4 + 2] = m.z ? a.z : NEG_FILL;
        x[v * 4 + 3] = m.w ? a.w : NEG_FILL;
    }

    __shared__ float2 red[WARPS];    // (S1, S2) per warp
    __shared__ float  sh_bcast[2];   // (tau / max, done)

    // ---- block max ----
    float mx = x[0];
    #pragma unroll
    for (int i = 1; i < EPT; ++i) mx = fmaxf(mx, x[i]);
    #pragma unroll
    for (int o = 16; o; o >>= 1) mx = fmaxf(mx, __shfl_xor_sync(0xffffffffu, mx, o));
    if (lane == 0) red[warp].x = mx;
    __syncthreads();
    if (tid == 0) {
        float v = red[0].x;
        #pragma unroll
        for (int w = 1; w < WARPS; ++w) v = fmaxf(v, red[w].x);
        sh_bcast[0] = v;
    }
    __syncthreads();
    mx = sh_bcast[0];

    // ---- alpha=1.5 transform: X = (x - max) * 0.5 so max(X) == 0 ----
    const float mxh = mx * 0.5f;
    #pragma unroll
    for (int i = 0; i < EPT; ++i) x[i] = fmaf(x[i], 0.5f, -mxh);

    // ---- Newton-on-sqrt root find; tau* in [-1, 0) ----
    float tau = -1.0f;   // the max element alone contributes 1 => f(-1) >= 1

    #pragma unroll 1
    for (int it = 0; it < 20; ++it) {
        float s1a = 0.0f, s1b = 0.0f, s2a = 0.0f, s2b = 0.0f;
        #pragma unroll
        for (int i = 0; i < EPT; i += 2) {
            float d0 = fmaxf(x[i]     - tau, 0.0f);
            float d1 = fmaxf(x[i + 1] - tau, 0.0f);
            s1a += d0;                s1b += d1;
            s2a  = fmaf(d0, d0, s2a); s2b  = fmaf(d1, d1, s2b);
        }
        float s1 = s1a + s1b;
        float s2 = s2a + s2b;
        #pragma unroll
        for (int o = 16; o; o >>= 1) {
            s1 += __shfl_xor_sync(0xffffffffu, s1, o);
            s2 += __shfl_xor_sync(0xffffffffu, s2, o);
        }
        if (lane == 0) red[warp] = make_float2(s1, s2);
        __syncthreads();
        if (tid == 0) {
            float S1 = 0.0f, S2 = 0.0f;
            #pragma unroll
            for (int w = 0; w < WARPS; ++w) {
                float2 r = red[w];
                S1 += r.x; S2 += r.y;
            }
            // Newton on sqrt(f)-1: dlt = (S2 - sqrt(S2)) / S1
            float dlt = (S2 - sqrtf(S2)) / fmaxf(S1, 1e-20f);
            sh_bcast[0] = tau + dlt;
            sh_bcast[1] = (dlt < 1e-6f) ? 1.0f : 0.0f;
        }
        __syncthreads();
        tau = sh_bcast[0];
        if (sh_bcast[1] != 0.0f) break;
    }

    // ---- emit p = clip(X - tau, 0)^2 ----
    #pragma unroll
    for (int v = 0; v < V4; ++v) {
        float4 r;
        float d;
        d = fmaxf(x[v * 4 + 0] - tau, 0.0f); r.x = d * d;
        d = fmaxf(x[v * 4 + 1] - tau, 0.0f); r.y = d * d;
        d = fmaxf(x[v * 4 + 2] - tau, 0.0f); r.z = d * d;
        d = fmaxf(x[v * 4 + 3] - tau, 0.0f); r.w = d * d;
        o4[tid + v * THREADS] = r;
    }
}

extern "C" void kernel_launch(void* const* d_in, const int* in_sizes, int n_in,
                              void* d_out, int out_size)
{
    const float* scores = (const float*)d_in[0];
    const int*   mask   = (const int*)d_in[1];
    float*       out    = (float*)d_out;
    const int rows = in_sizes[0] / S_LEN;
    entmax15_kernel<<<rows, THREADS>>>(scores, mask, out);
}

// round 8
// speedup vs baseline: 1.2623x; 1.2623x over previous
#include <cuda_runtime.h>
#include <cuda_bf16.h>

// Entmax15: out = clip(X - tau*, 0)^2 with sum(out) = 1 per row,
// X = (masked_scores - rowmax) * 0.5.
//
// tau* via Newton on g(tau) = sqrt(f(tau)) - 1, f(tau) = sum max(X-tau,0)^2.
// g is convex left of the root (each piece of f is K(t-c)^2+v so
// 2 f f'' - f'^2 = 4Kv >= 0, g' continuous nondecreasing), hence Newton from
// tau = -1 is monotone and never overshoots: dlt = (S2 - sqrt(S2)) / S1.
//
// Shape: 128 threads x 16 elems (R7 lesson: per-thread front-batched LDG
// depth, not occupancy, drives achieved HBM BW on this kernel).
// Solve loop: ONE barrier per iteration. Warp leaders STS (S1,S2) into a
// double-buffered slot; after the barrier EVERY thread combines the 4 warp
// partials (broadcast LDS, 4 warps only -> cheap) and computes tau locally.
// Identical FP ops on identical inputs => tau is bitwise-uniform across the
// block, so the loop-exit decision needs no broadcast. Double buffering makes
// the single-barrier scheme race-free (iter i+2's write to buffer p is
// separated from iter i's reads by iter i+1's barrier).
// redux.sync.f32 unavailable on sm_103a (R5) -> shuffle-tree warp reduce.

constexpr int S_LEN   = 2048;
constexpr int THREADS = 128;
constexpr int WARPS   = THREADS / 32;
constexpr int EPT     = S_LEN / THREADS;      // 16 elems per thread
constexpr int V4      = EPT / 4;              // 4 float4 per thread
constexpr float NEG_FILL = -1e4f;

__global__ void __launch_bounds__(THREADS, 8)
entmax15_kernel(const float* __restrict__ scores,
                const int*   __restrict__ mask,
                float*       __restrict__ out)
{
    const long long base = (long long)blockIdx.x * S_LEN;
    const float4* s4 = reinterpret_cast<const float4*>(scores + base);
    const int4*   m4 = reinterpret_cast<const int4*>(mask + base);
    float4*       o4 = reinterpret_cast<float4*>(out + base);

    const int tid  = threadIdx.x;
    const int warp = tid >> 5;
    const int lane = tid & 31;

    // ---- load 16 elems/thread (front-batched), apply mask ----
    float x[EPT];
    #pragma unroll
    for (int v = 0; v < V4; ++v) {
        float4 a = s4[tid + v * THREADS];
        int4   m = m4[tid + v * THREADS];
        x[v * 4 + 0] = m.x ? a.x : NEG_FILL;
        x[v * 4 + 1] = m.y ? a.y : NEG_FILL;
        x[v * 4 + 2] = m.z ? a.z : NEG_FILL;
        x[v * 4 + 3] = m.w ? a.w : NEG_FILL;
    }

    __shared__ float  shmax[WARPS];
    __shared__ float2 red[2][WARPS];   // double-buffered (S1, S2) per warp

    // ---- block max: one barrier, every thread combines the 4 warp maxes ----
    float mx = x[0];
    #pragma unroll
    for (int i = 1; i < EPT; ++i) mx = fmaxf(mx, x[i]);
    #pragma unroll
    for (int o = 16; o; o >>= 1) mx = fmaxf(mx, __shfl_xor_sync(0xffffffffu, mx, o));
    if (lane == 0) shmax[warp] = mx;
    __syncthreads();
    mx = fmaxf(fmaxf(shmax[0], shmax[1]), fmaxf(shmax[2], shmax[3]));

    // ---- alpha=1.5 transform: X = (x - max) * 0.5 so max(X) == 0 ----
    const float mxh = mx * 0.5f;
    #pragma unroll
    for (int i = 0; i < EPT; ++i) x[i] = fmaf(x[i], 0.5f, -mxh);

    // ---- Newton-on-sqrt root find; tau* in [-1, 0) ----
    float tau = -1.0f;   // the max element alone contributes 1 => f(-1) >= 1
    int   p   = 0;

    #pragma unroll 1
    for (int it = 0; it < 20; ++it) {
        float s1a = 0.0f, s1b = 0.0f, s2a = 0.0f, s2b = 0.0f;
        #pragma unroll
        for (int i = 0; i < EPT; i += 2) {
            float d0 = fmaxf(x[i]     - tau, 0.0f);
            float d1 = fmaxf(x[i + 1] - tau, 0.0f);
            s1a += d0;                s1b += d1;
            s2a  = fmaf(d0, d0, s2a); s2b  = fmaf(d1, d1, s2b);
        }
        float s1 = s1a + s1b;
        float s2 = s2a + s2b;
        #pragma unroll
        for (int o = 16; o; o >>= 1) {
            s1 += __shfl_xor_sync(0xffffffffu, s1, o);
            s2 += __shfl_xor_sync(0xffffffffu, s2, o);
        }
        if (lane == 0) red[p][warp] = make_float2(s1, s2);
        __syncthreads();

        float2 r0 = red[p][0], r1 = red[p][1], r2 = red[p][2], r3 = red[p][3];
        float S1 = (r0.x + r1.x) + (r2.x + r3.x);
        float S2 = (r0.y + r1.y) + (r2.y + r3.y);
        p ^= 1;

        // Newton on sqrt(f)-1: dlt = (S2 - sqrt(S2)) / S1.
        // Uniform inputs + uniform ops -> tau identical across all threads.
        float dlt = __fdividef(S2 - sqrtf(S2), fmaxf(S1, 1e-20f));
        tau += dlt;
        if (dlt < 1e-6f) break;
    }

    // ---- emit p = clip(X - tau, 0)^2 ----
    #pragma unroll
    for (int v = 0; v < V4; ++v) {
        float4 r;
        float d;
        d = fmaxf(x[v * 4 + 0] - tau, 0.0f); r.x = d * d;
        d = fmaxf(x[v * 4 + 1] - tau, 0.0f); r.y = d * d;
        d = fmaxf(x[v * 4 + 2] - tau, 0.0f); r.z = d * d;
        d = fmaxf(x[v * 4 + 3] - tau, 0.0f); r.w = d * d;
        o4[tid + v * THREADS] = r;
    }
}

extern "C" void kernel_launch(void* const* d_in, const int* in_sizes, int n_in,
                              void* d_out, int out_size)
{
    const float* scores = (const float*)d_in[0];
    const int*   mask   = (const int*)d_in[1];
    float*       out    = (float*)d_out;
    const int rows = in_sizes[0] / S_LEN;
    entmax15_kernel<<<rows, THREADS>>>(scores, mask, out);
}